// round 1
// baseline (speedup 1.0000x reference)
#include <cuda_runtime.h>

// Problem constants
#define BB   2
#define TT   2048
#define DIMC 1024
#define NH   16
#define HD   64
#define MTOT (BB * TT)          // 4096
#define N_QKV (3 * DIMC)        // 3072

// -------- scratch (device globals; no allocation allowed) --------
__device__ float g_q[BB * NH * TT * HD];     // [B,H,T,D]
__device__ float g_k[BB * NH * TT * HD];
__device__ float g_v[BB * NH * TT * HD];
__device__ float g_att[BB * TT * DIMC];      // [B,T,C]

// ============================================================================
// SGEMM: C[M,N] = A[M,1024] @ B[1024,N] + bias
// 128x128 block tile, BK=16, 256 threads, 8x8 micro-tile.
// MODE 1: A = x, scatter epilogue -> g_q (+pos_bias), g_k, g_v in [B,H,T,D]
// MODE 0: A = g_att, plain epilogue -> Cout (+bias)
// ============================================================================
template <int MODE>
__global__ __launch_bounds__(256) void sgemm_kernel(
    const float* __restrict__ Ain, const float* __restrict__ Bw,
    const float* __restrict__ bias, const float* __restrict__ pos,
    float* __restrict__ Cout, int N)
{
    const int K = DIMC;
    __shared__ float sA[16][128];   // transposed A tile: sA[k][m]
    __shared__ float sB[16][128];   // sB[k][n]

    const float* A = (MODE == 0) ? g_att : Ain;

    int tid = threadIdx.x;
    int tx = tid & 15;          // 0..15  -> 8 cols each
    int ty = tid >> 4;          // 0..15  -> 8 rows each
    int row0 = blockIdx.y * 128;
    int col0 = blockIdx.x * 128;

    int aRow  = tid >> 2;           // 0..63 (two passes -> 128 rows)
    int aCol4 = (tid & 3) << 2;     // 0,4,8,12
    int bRow  = tid >> 5;           // 0..7  (two passes -> 16 rows)
    int bCol4 = (tid & 31) << 2;    // 0..124

    float acc[8][8];
#pragma unroll
    for (int i = 0; i < 8; ++i)
#pragma unroll
        for (int j = 0; j < 8; ++j) acc[i][j] = 0.0f;

    for (int k0 = 0; k0 < K; k0 += 16) {
#pragma unroll
        for (int r = 0; r < 2; ++r) {
            int ar = aRow + (r << 6);
            float4 v = *(const float4*)(A + (size_t)(row0 + ar) * K + k0 + aCol4);
            sA[aCol4 + 0][ar] = v.x;
            sA[aCol4 + 1][ar] = v.y;
            sA[aCol4 + 2][ar] = v.z;
            sA[aCol4 + 3][ar] = v.w;
        }
#pragma unroll
        for (int r = 0; r < 2; ++r) {
            int br = bRow + (r << 3);
            *(float4*)&sB[br][bCol4] =
                *(const float4*)(Bw + (size_t)(k0 + br) * N + col0 + bCol4);
        }
        __syncthreads();

#pragma unroll
        for (int kk = 0; kk < 16; ++kk) {
            float a[8], b[8];
            *(float4*)&a[0] = *(const float4*)&sA[kk][ty * 8];
            *(float4*)&a[4] = *(const float4*)&sA[kk][ty * 8 + 4];
            *(float4*)&b[0] = *(const float4*)&sB[kk][tx * 8];
            *(float4*)&b[4] = *(const float4*)&sB[kk][tx * 8 + 4];
#pragma unroll
            for (int i = 0; i < 8; ++i)
#pragma unroll
                for (int j = 0; j < 8; ++j)
                    acc[i][j] = fmaf(a[i], b[j], acc[i][j]);
        }
        __syncthreads();
    }

    // epilogue
#pragma unroll
    for (int i = 0; i < 8; ++i) {
        int m = row0 + ty * 8 + i;
#pragma unroll
        for (int j = 0; j < 8; ++j) {
            int n = col0 + tx * 8 + j;
            float val = acc[i][j] + bias[n];
            if (MODE == 0) {
                Cout[(size_t)m * N + n] = val;
            } else {
                int sec = n >> 10;              // 0:q 1:k 2:v
                int c = n & 1023;
                int h = c >> 6, d = c & 63;
                int b_ = m >> 11, t = m & 2047; // T = 2048
                size_t idx = (((size_t)(b_ * NH + h)) * TT + t) * HD + d;
                if (sec == 0)      g_q[idx] = val + pos[(h << 6) + d];
                else if (sec == 1) g_k[idx] = val;
                else               g_v[idx] = val;
            }
        }
    }
}

// ============================================================================
// Flash attention, fp32. One block per (q-tile of 64, b*h). 256 threads.
// Online softmax; S staged through SMEM; 4x4 register micro-tiles.
// ============================================================================
struct AttnSmem {
    float Qt[64][64];   // transposed: Qt[d][row]
    float Kt[64][64];   // transposed: Kt[d][col]
    float V [64][64];   // row-major:  V[krow][d]
    float S [64][68];   // padded rows (softmax column scans)
    float mrow[64];
    float lrow[64];
    float arow[64];
};

__global__ __launch_bounds__(256) void attn_kernel()
{
    extern __shared__ char smraw[];
    AttnSmem& sm = *reinterpret_cast<AttnSmem*>(smraw);

    int tid = threadIdx.x;
    int tx = tid & 15;          // 4 cols each
    int ty = tid >> 4;          // 4 rows each
    int iq = blockIdx.x;
    int bh = blockIdx.y;
    int q0 = iq * 64;
    const float scale = 0.125f; // 1/sqrt(64)

    const float* qb = g_q + (size_t)bh * TT * HD;
    const float* kb = g_k + (size_t)bh * TT * HD;
    const float* vb = g_v + (size_t)bh * TT * HD;

    // load Q tile transposed
#pragma unroll
    for (int it = 0; it < 4; ++it) {
        int idx = tid + it * 256;
        int r = idx >> 4;
        int c4 = (idx & 15) << 2;
        float4 v = *(const float4*)(qb + (size_t)(q0 + r) * HD + c4);
        sm.Qt[c4 + 0][r] = v.x;
        sm.Qt[c4 + 1][r] = v.y;
        sm.Qt[c4 + 2][r] = v.z;
        sm.Qt[c4 + 3][r] = v.w;
    }
    if (tid < 64) { sm.mrow[tid] = -1e30f; sm.lrow[tid] = 0.0f; }

    float O[4][4] = {{0.0f}};

    for (int ik = 0; ik <= iq; ++ik) {
        int k0 = ik * 64;
        __syncthreads();   // previous iteration's consumers of Kt/V/S done
#pragma unroll
        for (int it = 0; it < 4; ++it) {
            int idx = tid + it * 256;
            int r = idx >> 4;
            int c4 = (idx & 15) << 2;
            float4 kv = *(const float4*)(kb + (size_t)(k0 + r) * HD + c4);
            sm.Kt[c4 + 0][r] = kv.x;
            sm.Kt[c4 + 1][r] = kv.y;
            sm.Kt[c4 + 2][r] = kv.z;
            sm.Kt[c4 + 3][r] = kv.w;
            float4 vv = *(const float4*)(vb + (size_t)(k0 + r) * HD + c4);
            *(float4*)&sm.V[r][c4] = vv;
        }
        __syncthreads();

        // S = Q K^T (4x4 per thread)
        float cS[4][4] = {{0.0f}};
#pragma unroll 8
        for (int d = 0; d < 64; ++d) {
            float a[4], b[4];
            *(float4*)a = *(const float4*)&sm.Qt[d][ty << 2];
            *(float4*)b = *(const float4*)&sm.Kt[d][tx << 2];
#pragma unroll
            for (int i = 0; i < 4; ++i)
#pragma unroll
                for (int j = 0; j < 4; ++j)
                    cS[i][j] = fmaf(a[i], b[j], cS[i][j]);
        }

        bool diag = (ik == iq);
#pragma unroll
        for (int i = 0; i < 4; ++i) {
            float tmp[4];
#pragma unroll
            for (int j = 0; j < 4; ++j) {
                float v = cS[i][j] * scale;
                if (diag && (k0 + (tx << 2) + j > q0 + (ty << 2) + i)) v = -1e30f;
                tmp[j] = v;
            }
            *(float4*)&sm.S[(ty << 2) + i][tx << 2] = *(float4*)tmp;
        }
        __syncthreads();

        // online softmax: one thread per row
        if (tid < 64) {
            int r = tid;
            float mo = sm.mrow[r];
            float mx = mo;
#pragma unroll 8
            for (int c = 0; c < 64; ++c) mx = fmaxf(mx, sm.S[r][c]);
            float al = __expf(mo - mx);
            float ps = 0.0f;
#pragma unroll 8
            for (int c = 0; c < 64; ++c) {
                float p = __expf(sm.S[r][c] - mx);
                sm.S[r][c] = p;
                ps += p;
            }
            sm.mrow[r] = mx;
            sm.lrow[r] = sm.lrow[r] * al + ps;
            sm.arow[r] = al;
        }
        __syncthreads();

        // O = O*alpha + P @ V
        float al[4];
#pragma unroll
        for (int i = 0; i < 4; ++i) al[i] = sm.arow[(ty << 2) + i];
#pragma unroll
        for (int i = 0; i < 4; ++i)
#pragma unroll
            for (int j = 0; j < 4; ++j) O[i][j] *= al[i];

#pragma unroll 4
        for (int j0 = 0; j0 < 64; ++j0) {
            float bv[4];
            *(float4*)bv = *(const float4*)&sm.V[j0][tx << 2];
            float a0 = sm.S[(ty << 2) + 0][j0];
            float a1 = sm.S[(ty << 2) + 1][j0];
            float a2 = sm.S[(ty << 2) + 2][j0];
            float a3 = sm.S[(ty << 2) + 3][j0];
#pragma unroll
            for (int j = 0; j < 4; ++j) {
                O[0][j] = fmaf(a0, bv[j], O[0][j]);
                O[1][j] = fmaf(a1, bv[j], O[1][j]);
                O[2][j] = fmaf(a2, bv[j], O[2][j]);
                O[3][j] = fmaf(a3, bv[j], O[3][j]);
            }
        }
    }

    // normalize and write [B,T,C] for out-proj
    int b_ = bh >> 4, h = bh & 15;
#pragma unroll
    for (int i = 0; i < 4; ++i) {
        int t = q0 + (ty << 2) + i;
        float inv = 1.0f / sm.lrow[(ty << 2) + i];
        float tmp[4];
#pragma unroll
        for (int j = 0; j < 4; ++j) tmp[j] = O[i][j] * inv;
        *(float4*)(g_att + ((size_t)(b_ * TT + t)) * DIMC + (h << 6) + (tx << 2)) =
            *(float4*)tmp;
    }
}

// ============================================================================
// Launch
// ============================================================================
extern "C" void kernel_launch(void* const* d_in, const int* in_sizes, int n_in,
                              void* d_out, int out_size)
{
    (void)in_sizes; (void)n_in; (void)out_size;
    const float* x     = (const float*)d_in[0];
    const float* w_qkv = (const float*)d_in[1];
    const float* b_qkv = (const float*)d_in[2];
    const float* w_out = (const float*)d_in[3];
    const float* b_out = (const float*)d_in[4];
    const float* pos   = (const float*)d_in[5];
    float* out = (float*)d_out;

    cudaFuncSetAttribute(attn_kernel, cudaFuncAttributeMaxDynamicSharedMemorySize,
                         (int)sizeof(AttnSmem));

    // 1) QKV projection + bias + pos_bias + head-split/transpose
    dim3 gq(N_QKV / 128, MTOT / 128);     // (24, 32)
    sgemm_kernel<1><<<gq, 256>>>(x, w_qkv, b_qkv, pos, nullptr, N_QKV);

    // 2) causal flash attention
    attn_kernel<<<dim3(TT / 64, BB * NH), 256, sizeof(AttnSmem)>>>();

    // 3) output projection + bias
    dim3 gp(DIMC / 128, MTOT / 128);      // (8, 32)
    sgemm_kernel<0><<<gp, 256>>>(nullptr, w_out, b_out, nullptr, out, DIMC);
}

// round 3
// speedup vs baseline: 1.4486x; 1.4486x over previous
#include <cuda_runtime.h>
#include <cuda_bf16.h>
#include <cstdint>

// Problem constants
#define BB   2
#define TT   2048
#define DIMC 1024
#define NH   16
#define HD   64
#define MTOT (BB * TT)          // 4096
#define N_QKV (3 * DIMC)        // 3072

// -------- scratch (device globals; no allocation allowed) --------
__device__ float g_q[BB * NH * TT * HD];     // [B,H,T,D] fp32
__device__ float g_k[BB * NH * TT * HD];
__device__ float g_v[BB * NH * TT * HD];
__device__ float g_att[BB * TT * DIMC];      // [B,T,C] fp32

// bf16 split operands
__device__ __nv_bfloat16 g_xh[MTOT * DIMC], g_xl[MTOT * DIMC];        // x
__device__ __nv_bfloat16 g_ah[MTOT * DIMC], g_al[MTOT * DIMC];        // attn out
__device__ __nv_bfloat16 g_wqh[N_QKV * DIMC], g_wql[N_QKV * DIMC];    // W_qkv^T [3072,1024]
__device__ __nv_bfloat16 g_woh[DIMC * DIMC], g_wol[DIMC * DIMC];      // W_out^T [1024,1024]

// ============================================================================
// Helpers (plain-target PTX: cp.async / ldmatrix / mma.sync — no tcgen05)
// ============================================================================
__device__ __forceinline__ uint32_t smem_u32(const void* p) {
    uint32_t a;
    asm("{ .reg .u64 t; cvta.to.shared.u64 t, %1; cvt.u32.u64 %0, t; }" : "=r"(a) : "l"(p));
    return a;
}
__device__ __forceinline__ void cp16(uint32_t dst, const void* src) {
    asm volatile("cp.async.cg.shared.global [%0], [%1], 16;" :: "r"(dst), "l"(src));
}
__device__ __forceinline__ void cp_commit() { asm volatile("cp.async.commit_group;" ::: "memory"); }
__device__ __forceinline__ void cp_wait0()  { asm volatile("cp.async.wait_group 0;" ::: "memory"); }
__device__ __forceinline__ void cp_wait1()  { asm volatile("cp.async.wait_group 1;" ::: "memory"); }

__device__ __forceinline__ void ldsm4(uint32_t& r0, uint32_t& r1, uint32_t& r2, uint32_t& r3,
                                      uint32_t addr) {
    asm volatile("ldmatrix.sync.aligned.m8n8.x4.shared.b16 {%0,%1,%2,%3}, [%4];"
                 : "=r"(r0), "=r"(r1), "=r"(r2), "=r"(r3) : "r"(addr));
}
__device__ __forceinline__ void ldsm2(uint32_t& r0, uint32_t& r1, uint32_t addr) {
    asm volatile("ldmatrix.sync.aligned.m8n8.x2.shared.b16 {%0,%1}, [%2];"
                 : "=r"(r0), "=r"(r1) : "r"(addr));
}
__device__ __forceinline__ void mma16816(float* c, const uint32_t* a, const uint32_t* b) {
    asm volatile(
        "mma.sync.aligned.m16n8k16.row.col.f32.bf16.bf16.f32 "
        "{%0,%1,%2,%3}, {%4,%5,%6,%7}, {%8,%9}, {%0,%1,%2,%3};"
        : "+f"(c[0]), "+f"(c[1]), "+f"(c[2]), "+f"(c[3])
        : "r"(a[0]), "r"(a[1]), "r"(a[2]), "r"(a[3]), "r"(b[0]), "r"(b[1]));
}

// ============================================================================
// fp32 -> bf16 split conversion  (W=0: x -> g_xh/g_xl ; W=1: g_att -> g_ah/g_al)
// ============================================================================
template <int W>
__global__ void split_kernel(const float* __restrict__ src_arg) {
    int i = blockIdx.x * blockDim.x + threadIdx.x;
    const float* src = (W == 0) ? src_arg : g_att;
    __nv_bfloat16* hi = (W == 0) ? g_xh : g_ah;
    __nv_bfloat16* lo = (W == 0) ? g_xl : g_al;
    float v = src[i];
    __nv_bfloat16 h = __float2bfloat16(v);
    hi[i] = h;
    lo[i] = __float2bfloat16(v - __bfloat162float(h));
}

// ============================================================================
// W[K=1024, N] -> W^T split into [N, 1024] bf16 hi/lo
// ============================================================================
template <int W>
__global__ void transpose_split(const float* __restrict__ Win) {
    const int N = (W == 0) ? N_QKV : DIMC;
    __nv_bfloat16* Th = (W == 0) ? g_wqh : g_woh;
    __nv_bfloat16* Tl = (W == 0) ? g_wql : g_wol;
    __shared__ float t[32][33];
    int tx = threadIdx.x, ty = threadIdx.y;
    int n0 = blockIdx.x * 32, k0 = blockIdx.y * 32;
#pragma unroll
    for (int j = 0; j < 32; j += 8)
        t[ty + j][tx] = Win[(size_t)(k0 + ty + j) * N + n0 + tx];
    __syncthreads();
#pragma unroll
    for (int j = 0; j < 32; j += 8) {
        float v = t[tx][ty + j];                 // W[k0+tx][n0+ty+j]
        size_t o = (size_t)(n0 + ty + j) * DIMC + k0 + tx;
        __nv_bfloat16 h = __float2bfloat16(v);
        Th[o] = h;
        Tl[o] = __float2bfloat16(v - __bfloat162float(h));
    }
}

// ============================================================================
// HMMA split-bf16 GEMM: C[M,N] = A[M,1024] @ B^T[N,1024]  (3-product split)
// 128x128 CTA tile, BK=32, 256 threads (8 warps, 2x4 grid, 64x32 warp tiles),
// mma.sync m16n8k16 bf16, ldmatrix, 2-stage cp.async double buffer.
// MODE 1: A = x (xh/xl), B = Wqkv^T; scatter epilogue -> g_q(+pos)/g_k/g_v
// MODE 0: A = attn out (ah/al), B = Wout^T; epilogue -> Cout (+bias)
// ============================================================================
#define PADK   40                  // 32 + 8 bf16 padding (80B rows, ldmatrix conflict-free)
#define MAT_B  (128 * PADK * 2)    // one 128x32 bf16 tile (padded) = 10240 B
#define STG_B  (4 * MAT_B)         // Ah, Al, Bh, Bl = 40960 B
#define GEMM_SMEM (2 * STG_B)      // 81920 B

template <int MODE>
__global__ __launch_bounds__(256) void hmma_gemm(
    const float* __restrict__ bias, const float* __restrict__ pos,
    float* __restrict__ Cout)
{
    const __nv_bfloat16* Ah = (MODE == 1) ? g_xh : g_ah;
    const __nv_bfloat16* Al = (MODE == 1) ? g_xl : g_al;
    const __nv_bfloat16* Bh = (MODE == 1) ? g_wqh : g_woh;
    const __nv_bfloat16* Bl = (MODE == 1) ? g_wql : g_wol;

    extern __shared__ char smraw[];
    const uint32_t sbase = smem_u32(smraw);

    const int tid = threadIdx.x;
    const int wid = tid >> 5, lane = tid & 31;
    const int wm0 = (wid >> 2) * 64;     // warp m offset in CTA tile
    const int wn0 = (wid & 3) * 32;      // warp n offset in CTA tile

    const int row0 = blockIdx.y * 128;
    const int col0 = blockIdx.x * 128;

    const __nv_bfloat16* srcs[4] = {
        Ah + (size_t)row0 * DIMC, Al + (size_t)row0 * DIMC,
        Bh + (size_t)col0 * DIMC, Bl + (size_t)col0 * DIMC };

    // per-thread load positions: 512 cp16 per matrix / 256 threads = 2 each
    const int lr0 = tid >> 2;            // rows tid/4 and tid/4+64
    const int lch = tid & 3;             // 16B chunk within 64B row segment

    auto load_chunk = [&](int kc, int s) {
        uint32_t st = sbase + (uint32_t)s * STG_B;
#pragma unroll
        for (int mmat = 0; mmat < 4; ++mmat) {
            const __nv_bfloat16* src = srcs[mmat] + (size_t)kc * 32;
            uint32_t mb = st + (uint32_t)mmat * MAT_B;
#pragma unroll
            for (int i = 0; i < 2; ++i) {
                int r = lr0 + i * 64;
                cp16(mb + (uint32_t)(r * PADK + lch * 8) * 2,
                     src + (size_t)r * DIMC + lch * 8);
            }
        }
    };

    float acc[4][4][4];
#pragma unroll
    for (int i = 0; i < 4; ++i)
#pragma unroll
        for (int j = 0; j < 4; ++j)
#pragma unroll
            for (int k = 0; k < 4; ++k) acc[i][j][k] = 0.0f;

    // ldmatrix address components
    const int aRow = lane & 15;               // row within 16-row frag
    const int aColHalf = (lane >> 4) * 8;     // 0 or 8 (k)
    const int bRow = lane & 7;                // row within 8-row frag (n)
    const int bColHalf = ((lane >> 3) & 1) * 8;

    load_chunk(0, 0);
    cp_commit();

    const int NC = DIMC / 32;   // 32
    for (int kc = 0; kc < NC; ++kc) {
        int cur = kc & 1;
        if (kc + 1 < NC) {
            load_chunk(kc + 1, cur ^ 1);
            cp_commit();
            cp_wait1();
        } else {
            cp_wait0();
        }
        __syncthreads();

        uint32_t st = sbase + (uint32_t)cur * STG_B;
        uint32_t aH = st;
        uint32_t aL = st + MAT_B;
        uint32_t bH = st + 2 * MAT_B;
        uint32_t bL = st + 3 * MAT_B;

#pragma unroll
        for (int ks = 0; ks < 2; ++ks) {
            uint32_t ah[4][4], al[4][4], bh[4][2], bl[4][2];
            int kcol = ks * 16;
#pragma unroll
            for (int mf = 0; mf < 4; ++mf) {
                uint32_t off = (uint32_t)((wm0 + mf * 16 + aRow) * PADK + kcol + aColHalf) * 2;
                ldsm4(ah[mf][0], ah[mf][1], ah[mf][2], ah[mf][3], aH + off);
                ldsm4(al[mf][0], al[mf][1], al[mf][2], al[mf][3], aL + off);
            }
#pragma unroll
            for (int nf = 0; nf < 4; ++nf) {
                uint32_t off = (uint32_t)((wn0 + nf * 8 + bRow) * PADK + kcol + bColHalf) * 2;
                ldsm2(bh[nf][0], bh[nf][1], bH + off);
                ldsm2(bl[nf][0], bl[nf][1], bL + off);
            }
#pragma unroll
            for (int mf = 0; mf < 4; ++mf)
#pragma unroll
                for (int nf = 0; nf < 4; ++nf) {
                    mma16816(acc[mf][nf], ah[mf], bh[nf]);
                    mma16816(acc[mf][nf], ah[mf], bl[nf]);
                    mma16816(acc[mf][nf], al[mf], bh[nf]);
                }
        }
        __syncthreads();
    }

    // epilogue: acc thread layout — c0,c1: (row=lane/4, col=(lane%4)*2), c2,c3: row+8
    const int erow = lane >> 2;
    const int ecol = (lane & 3) * 2;
#pragma unroll
    for (int mf = 0; mf < 4; ++mf) {
#pragma unroll
        for (int half = 0; half < 2; ++half) {
            int m = row0 + wm0 + mf * 16 + erow + half * 8;
            int b_ = m >> 11, t = m & (TT - 1);
#pragma unroll
            for (int nf = 0; nf < 4; ++nf) {
                int n = col0 + wn0 + nf * 8 + ecol;
                float2 v;
                v.x = acc[mf][nf][half * 2 + 0] + bias[n + 0];
                v.y = acc[mf][nf][half * 2 + 1] + bias[n + 1];
                if (MODE == 0) {
                    *(float2*)(Cout + (size_t)m * DIMC + n) = v;
                } else {
                    int sec = n >> 10;
                    int cc = n & (DIMC - 1);
                    int h = cc >> 6, d = cc & 63;
                    size_t idx = (((size_t)(b_ * NH + h)) * TT + t) * HD + d;
                    if (sec == 0) {
                        v.x += pos[cc + 0];
                        v.y += pos[cc + 1];
                        *(float2*)(g_q + idx) = v;
                    } else if (sec == 1) {
                        *(float2*)(g_k + idx) = v;
                    } else {
                        *(float2*)(g_v + idx) = v;
                    }
                }
            }
        }
    }
}

// ============================================================================
// Flash attention, fp32 (unchanged).
// ============================================================================
struct AttnSmem {
    float Qt[64][64];
    float Kt[64][64];
    float V [64][64];
    float S [64][68];
    float mrow[64];
    float lrow[64];
    float arow[64];
};

__global__ __launch_bounds__(256) void attn_kernel()
{
    extern __shared__ char smraw[];
    AttnSmem& sm = *reinterpret_cast<AttnSmem*>(smraw);

    int tid = threadIdx.x;
    int tx = tid & 15;
    int ty = tid >> 4;
    int iq = blockIdx.x;
    int bh = blockIdx.y;
    int q0 = iq * 64;
    const float scale = 0.125f;

    const float* qb = g_q + (size_t)bh * TT * HD;
    const float* kb = g_k + (size_t)bh * TT * HD;
    const float* vb = g_v + (size_t)bh * TT * HD;

#pragma unroll
    for (int it = 0; it < 4; ++it) {
        int idx = tid + it * 256;
        int r = idx >> 4;
        int c4 = (idx & 15) << 2;
        float4 v = *(const float4*)(qb + (size_t)(q0 + r) * HD + c4);
        sm.Qt[c4 + 0][r] = v.x;
        sm.Qt[c4 + 1][r] = v.y;
        sm.Qt[c4 + 2][r] = v.z;
        sm.Qt[c4 + 3][r] = v.w;
    }
    if (tid < 64) { sm.mrow[tid] = -1e30f; sm.lrow[tid] = 0.0f; }

    float O[4][4] = {{0.0f}};

    for (int ik = 0; ik <= iq; ++ik) {
        int k0 = ik * 64;
        __syncthreads();
#pragma unroll
        for (int it = 0; it < 4; ++it) {
            int idx = tid + it * 256;
            int r = idx >> 4;
            int c4 = (idx & 15) << 2;
            float4 kv = *(const float4*)(kb + (size_t)(k0 + r) * HD + c4);
            sm.Kt[c4 + 0][r] = kv.x;
            sm.Kt[c4 + 1][r] = kv.y;
            sm.Kt[c4 + 2][r] = kv.z;
            sm.Kt[c4 + 3][r] = kv.w;
            float4 vv = *(const float4*)(vb + (size_t)(k0 + r) * HD + c4);
            *(float4*)&sm.V[r][c4] = vv;
        }
        __syncthreads();

        float cS[4][4] = {{0.0f}};
#pragma unroll 8
        for (int d = 0; d < 64; ++d) {
            float a[4], b[4];
            *(float4*)a = *(const float4*)&sm.Qt[d][ty << 2];
            *(float4*)b = *(const float4*)&sm.Kt[d][tx << 2];
#pragma unroll
            for (int i = 0; i < 4; ++i)
#pragma unroll
                for (int j = 0; j < 4; ++j)
                    cS[i][j] = fmaf(a[i], b[j], cS[i][j]);
        }

        bool diag = (ik == iq);
#pragma unroll
        for (int i = 0; i < 4; ++i) {
            float tmp[4];
#pragma unroll
            for (int j = 0; j < 4; ++j) {
                float v = cS[i][j] * scale;
                if (diag && (k0 + (tx << 2) + j > q0 + (ty << 2) + i)) v = -1e30f;
                tmp[j] = v;
            }
            *(float4*)&sm.S[(ty << 2) + i][tx << 2] = *(float4*)tmp;
        }
        __syncthreads();

        if (tid < 64) {
            int r = tid;
            float mo = sm.mrow[r];
            float mx = mo;
#pragma unroll 8
            for (int c = 0; c < 64; ++c) mx = fmaxf(mx, sm.S[r][c]);
            float al = __expf(mo - mx);
            float ps = 0.0f;
#pragma unroll 8
            for (int c = 0; c < 64; ++c) {
                float p = __expf(sm.S[r][c] - mx);
                sm.S[r][c] = p;
                ps += p;
            }
            sm.mrow[r] = mx;
            sm.lrow[r] = sm.lrow[r] * al + ps;
            sm.arow[r] = al;
        }
        __syncthreads();

        float al[4];
#pragma unroll
        for (int i = 0; i < 4; ++i) al[i] = sm.arow[(ty << 2) + i];
#pragma unroll
        for (int i = 0; i < 4; ++i)
#pragma unroll
            for (int j = 0; j < 4; ++j) O[i][j] *= al[i];

#pragma unroll 4
        for (int j0 = 0; j0 < 64; ++j0) {
            float bv[4];
            *(float4*)bv = *(const float4*)&sm.V[j0][tx << 2];
            float a0 = sm.S[(ty << 2) + 0][j0];
            float a1 = sm.S[(ty << 2) + 1][j0];
            float a2 = sm.S[(ty << 2) + 2][j0];
            float a3 = sm.S[(ty << 2) + 3][j0];
#pragma unroll
            for (int j = 0; j < 4; ++j) {
                O[0][j] = fmaf(a0, bv[j], O[0][j]);
                O[1][j] = fmaf(a1, bv[j], O[1][j]);
                O[2][j] = fmaf(a2, bv[j], O[2][j]);
                O[3][j] = fmaf(a3, bv[j], O[3][j]);
            }
        }
    }

    int b_ = bh >> 4, h = bh & 15;
#pragma unroll
    for (int i = 0; i < 4; ++i) {
        int t = q0 + (ty << 2) + i;
        float inv = 1.0f / sm.lrow[(ty << 2) + i];
        float tmp[4];
#pragma unroll
        for (int j = 0; j < 4; ++j) tmp[j] = O[i][j] * inv;
        *(float4*)(g_att + ((size_t)(b_ * TT + t)) * DIMC + (h << 6) + (tx << 2)) =
            *(float4*)tmp;
    }
}

// ============================================================================
// Launch
// ============================================================================
extern "C" void kernel_launch(void* const* d_in, const int* in_sizes, int n_in,
                              void* d_out, int out_size)
{
    (void)in_sizes; (void)n_in; (void)out_size;
    const float* x     = (const float*)d_in[0];
    const float* w_qkv = (const float*)d_in[1];
    const float* b_qkv = (const float*)d_in[2];
    const float* w_out = (const float*)d_in[3];
    const float* b_out = (const float*)d_in[4];
    const float* pos   = (const float*)d_in[5];
    float* out = (float*)d_out;

    cudaFuncSetAttribute(attn_kernel, cudaFuncAttributeMaxDynamicSharedMemorySize,
                         (int)sizeof(AttnSmem));
    cudaFuncSetAttribute(hmma_gemm<1>, cudaFuncAttributeMaxDynamicSharedMemorySize,
                         GEMM_SMEM);
    cudaFuncSetAttribute(hmma_gemm<0>, cudaFuncAttributeMaxDynamicSharedMemorySize,
                         GEMM_SMEM);

    // 0) split inputs into bf16 hi/lo (+ transpose weights to [N,K])
    split_kernel<0><<<MTOT * DIMC / 256, 256>>>(x);
    transpose_split<0><<<dim3(N_QKV / 32, DIMC / 32), dim3(32, 8)>>>(w_qkv);
    transpose_split<1><<<dim3(DIMC / 32, DIMC / 32), dim3(32, 8)>>>(w_out);

    // 1) QKV projection (HMMA) + bias + pos_bias + head-split scatter
    hmma_gemm<1><<<dim3(N_QKV / 128, MTOT / 128), 256, GEMM_SMEM>>>(b_qkv, pos, nullptr);

    // 2) causal flash attention (fp32)
    attn_kernel<<<dim3(TT / 64, BB * NH), 256, sizeof(AttnSmem)>>>();

    // 3) split attention output, then output projection (HMMA) + bias
    split_kernel<1><<<MTOT * DIMC / 256, 256>>>(nullptr);
    hmma_gemm<0><<<dim3(DIMC / 128, MTOT / 128), 256, GEMM_SMEM>>>(b_out, nullptr, out);
}

// round 4
// speedup vs baseline: 2.8964x; 1.9995x over previous
#include <cuda_runtime.h>
#include <cuda_bf16.h>
#include <cuda_fp16.h>
#include <cstdint>

// Problem constants
#define BB   2
#define TT   2048
#define DIMC 1024
#define NH   16
#define HD   64
#define MTOT (BB * TT)          // 4096
#define N_QKV (3 * DIMC)        // 3072

// q pre-scale: 1/sqrt(64) * log2(e)
#define QSCALE 0.18033688011112042f

// -------- scratch (device globals; no allocation allowed) --------
// fp16 split Q/K/V in [B,H,T,D]
__device__ __half g_qh[BB * NH * TT * HD], g_ql[BB * NH * TT * HD];
__device__ __half g_kh[BB * NH * TT * HD], g_kl[BB * NH * TT * HD];
__device__ __half g_vh[BB * NH * TT * HD], g_vl[BB * NH * TT * HD];
// bf16 split GEMM operands
__device__ __nv_bfloat16 g_xh[MTOT * DIMC], g_xl[MTOT * DIMC];        // x
__device__ __nv_bfloat16 g_ah[MTOT * DIMC], g_al[MTOT * DIMC];        // attn out [B,T,C]
__device__ __nv_bfloat16 g_wqh[N_QKV * DIMC], g_wql[N_QKV * DIMC];    // W_qkv^T
__device__ __nv_bfloat16 g_woh[DIMC * DIMC], g_wol[DIMC * DIMC];      // W_out^T

// ============================================================================
// Helpers (plain-target PTX: cp.async / ldmatrix / mma.sync)
// ============================================================================
__device__ __forceinline__ uint32_t smem_u32(const void* p) {
    uint32_t a;
    asm("{ .reg .u64 t; cvta.to.shared.u64 t, %1; cvt.u32.u64 %0, t; }" : "=r"(a) : "l"(p));
    return a;
}
__device__ __forceinline__ void cp16(uint32_t dst, const void* src) {
    asm volatile("cp.async.cg.shared.global [%0], [%1], 16;" :: "r"(dst), "l"(src));
}
__device__ __forceinline__ void cp_commit() { asm volatile("cp.async.commit_group;" ::: "memory"); }
__device__ __forceinline__ void cp_wait0()  { asm volatile("cp.async.wait_group 0;" ::: "memory"); }
__device__ __forceinline__ void cp_wait1()  { asm volatile("cp.async.wait_group 1;" ::: "memory"); }

__device__ __forceinline__ void ldsm4(uint32_t& r0, uint32_t& r1, uint32_t& r2, uint32_t& r3,
                                      uint32_t addr) {
    asm volatile("ldmatrix.sync.aligned.m8n8.x4.shared.b16 {%0,%1,%2,%3}, [%4];"
                 : "=r"(r0), "=r"(r1), "=r"(r2), "=r"(r3) : "r"(addr));
}
__device__ __forceinline__ void ldsm4t(uint32_t& r0, uint32_t& r1, uint32_t& r2, uint32_t& r3,
                                       uint32_t addr) {
    asm volatile("ldmatrix.sync.aligned.m8n8.x4.trans.shared.b16 {%0,%1,%2,%3}, [%4];"
                 : "=r"(r0), "=r"(r1), "=r"(r2), "=r"(r3) : "r"(addr));
}
__device__ __forceinline__ void ldsm2(uint32_t& r0, uint32_t& r1, uint32_t addr) {
    asm volatile("ldmatrix.sync.aligned.m8n8.x2.shared.b16 {%0,%1}, [%2];"
                 : "=r"(r0), "=r"(r1) : "r"(addr));
}
__device__ __forceinline__ void mma_bf(float* c, const uint32_t* a, const uint32_t* b) {
    asm volatile(
        "mma.sync.aligned.m16n8k16.row.col.f32.bf16.bf16.f32 "
        "{%0,%1,%2,%3}, {%4,%5,%6,%7}, {%8,%9}, {%0,%1,%2,%3};"
        : "+f"(c[0]), "+f"(c[1]), "+f"(c[2]), "+f"(c[3])
        : "r"(a[0]), "r"(a[1]), "r"(a[2]), "r"(a[3]), "r"(b[0]), "r"(b[1]));
}
__device__ __forceinline__ void mma_fp(float* c, const uint32_t* a, uint32_t b0, uint32_t b1) {
    asm volatile(
        "mma.sync.aligned.m16n8k16.row.col.f32.f16.f16.f32 "
        "{%0,%1,%2,%3}, {%4,%5,%6,%7}, {%8,%9}, {%0,%1,%2,%3};"
        : "+f"(c[0]), "+f"(c[1]), "+f"(c[2]), "+f"(c[3])
        : "r"(a[0]), "r"(a[1]), "r"(a[2]), "r"(a[3]), "r"(b0), "r"(b1));
}

// exp2 on FFMA pipe: magic-number round + degree-5 Taylor, t <= 0
__device__ __forceinline__ float exp2p(float t) {
    t = fmaxf(t, -80.0f);
    float k = t + 12582912.0f;             // 1.5*2^23 (round-to-nearest int)
    int ik = __float_as_int(k) << 23;      // integer part into exponent position
    float f = t - (k - 12582912.0f);       // f in [-0.5, 0.5]
    float r = 1.3333558146e-3f;
    r = fmaf(r, f, 9.6181291076e-3f);
    r = fmaf(r, f, 5.5504108664e-2f);
    r = fmaf(r, f, 2.4022650696e-1f);
    r = fmaf(r, f, 6.9314718056e-1f);
    r = fmaf(r, f, 1.0f);
    return __int_as_float(__float_as_int(r) + ik);
}

__device__ __forceinline__ uint32_t packh2(__half a, __half b) {
    __half2 h = __halves2half2(a, b);
    return *(uint32_t*)&h;
}
// split pair (a,b) -> fp16 hi pair + fp16 residual pair
__device__ __forceinline__ void split2h(float a, float b, uint32_t& hi, uint32_t& lo) {
    __half ha = __float2half_rn(a), hb = __float2half_rn(b);
    hi = packh2(ha, hb);
    lo = packh2(__float2half_rn(a - __half2float(ha)),
                __float2half_rn(b - __half2float(hb)));
}

// ============================================================================
// fp32 -> bf16 split conversion (x)
// ============================================================================
__global__ void split_kernel(const float* __restrict__ src) {
    int i = blockIdx.x * blockDim.x + threadIdx.x;
    float v = src[i];
    __nv_bfloat16 h = __float2bfloat16(v);
    g_xh[i] = h;
    g_xl[i] = __float2bfloat16(v - __bfloat162float(h));
}

// ============================================================================
// W[K=1024, N] -> W^T split into [N, 1024] bf16 hi/lo
// ============================================================================
template <int W>
__global__ void transpose_split(const float* __restrict__ Win) {
    const int N = (W == 0) ? N_QKV : DIMC;
    __nv_bfloat16* Th = (W == 0) ? g_wqh : g_woh;
    __nv_bfloat16* Tl = (W == 0) ? g_wql : g_wol;
    __shared__ float t[32][33];
    int tx = threadIdx.x, ty = threadIdx.y;
    int n0 = blockIdx.x * 32, k0 = blockIdx.y * 32;
#pragma unroll
    for (int j = 0; j < 32; j += 8)
        t[ty + j][tx] = Win[(size_t)(k0 + ty + j) * N + n0 + tx];
    __syncthreads();
#pragma unroll
    for (int j = 0; j < 32; j += 8) {
        float v = t[tx][ty + j];
        size_t o = (size_t)(n0 + ty + j) * DIMC + k0 + tx;
        __nv_bfloat16 h = __float2bfloat16(v);
        Th[o] = h;
        Tl[o] = __float2bfloat16(v - __bfloat162float(h));
    }
}

// ============================================================================
// HMMA split-bf16 GEMM (as round 3). MODE 1 epilogue now writes fp16 hi/lo
// Q (pre-scaled, +pos) / K / V. MODE 0 -> Cout fp32 (+bias).
// ============================================================================
#define PADK   40
#define MAT_B  (128 * PADK * 2)
#define STG_B  (4 * MAT_B)
#define GEMM_SMEM (2 * STG_B)

template <int MODE>
__global__ __launch_bounds__(256) void hmma_gemm(
    const float* __restrict__ bias, const float* __restrict__ pos,
    float* __restrict__ Cout)
{
    const __nv_bfloat16* Ah = (MODE == 1) ? g_xh : g_ah;
    const __nv_bfloat16* Al = (MODE == 1) ? g_xl : g_al;
    const __nv_bfloat16* Bh = (MODE == 1) ? g_wqh : g_woh;
    const __nv_bfloat16* Bl = (MODE == 1) ? g_wql : g_wol;

    extern __shared__ char smraw[];
    const uint32_t sbase = smem_u32(smraw);

    const int tid = threadIdx.x;
    const int wid = tid >> 5, lane = tid & 31;
    const int wm0 = (wid >> 2) * 64;
    const int wn0 = (wid & 3) * 32;

    const int row0 = blockIdx.y * 128;
    const int col0 = blockIdx.x * 128;

    const __nv_bfloat16* srcs[4] = {
        Ah + (size_t)row0 * DIMC, Al + (size_t)row0 * DIMC,
        Bh + (size_t)col0 * DIMC, Bl + (size_t)col0 * DIMC };

    const int lr0 = tid >> 2;
    const int lch = tid & 3;

    auto load_chunk = [&](int kc, int s) {
        uint32_t st = sbase + (uint32_t)s * STG_B;
#pragma unroll
        for (int mmat = 0; mmat < 4; ++mmat) {
            const __nv_bfloat16* src = srcs[mmat] + (size_t)kc * 32;
            uint32_t mb = st + (uint32_t)mmat * MAT_B;
#pragma unroll
            for (int i = 0; i < 2; ++i) {
                int r = lr0 + i * 64;
                cp16(mb + (uint32_t)(r * PADK + lch * 8) * 2,
                     src + (size_t)r * DIMC + lch * 8);
            }
        }
    };

    float acc[4][4][4];
#pragma unroll
    for (int i = 0; i < 4; ++i)
#pragma unroll
        for (int j = 0; j < 4; ++j)
#pragma unroll
            for (int k = 0; k < 4; ++k) acc[i][j][k] = 0.0f;

    const int aRow = lane & 15;
    const int aColHalf = (lane >> 4) * 8;
    const int bRow = lane & 7;
    const int bColHalf = ((lane >> 3) & 1) * 8;

    load_chunk(0, 0);
    cp_commit();

    const int NC = DIMC / 32;
    for (int kc = 0; kc < NC; ++kc) {
        int cur = kc & 1;
        if (kc + 1 < NC) {
            load_chunk(kc + 1, cur ^ 1);
            cp_commit();
            cp_wait1();
        } else {
            cp_wait0();
        }
        __syncthreads();

        uint32_t st = sbase + (uint32_t)cur * STG_B;
        uint32_t aH = st, aL = st + MAT_B, bH = st + 2 * MAT_B, bL = st + 3 * MAT_B;

#pragma unroll
        for (int ks = 0; ks < 2; ++ks) {
            uint32_t ah[4][4], al[4][4], bh[4][2], bl[4][2];
            int kcol = ks * 16;
#pragma unroll
            for (int mf = 0; mf < 4; ++mf) {
                uint32_t off = (uint32_t)((wm0 + mf * 16 + aRow) * PADK + kcol + aColHalf) * 2;
                ldsm4(ah[mf][0], ah[mf][1], ah[mf][2], ah[mf][3], aH + off);
                ldsm4(al[mf][0], al[mf][1], al[mf][2], al[mf][3], aL + off);
            }
#pragma unroll
            for (int nf = 0; nf < 4; ++nf) {
                uint32_t off = (uint32_t)((wn0 + nf * 8 + bRow) * PADK + kcol + bColHalf) * 2;
                ldsm2(bh[nf][0], bh[nf][1], bH + off);
                ldsm2(bl[nf][0], bl[nf][1], bL + off);
            }
#pragma unroll
            for (int mf = 0; mf < 4; ++mf)
#pragma unroll
                for (int nf = 0; nf < 4; ++nf) {
                    mma_bf(acc[mf][nf], ah[mf], bh[nf]);
                    mma_bf(acc[mf][nf], ah[mf], bl[nf]);
                    mma_bf(acc[mf][nf], al[mf], bh[nf]);
                }
        }
        __syncthreads();
    }

    const int erow = lane >> 2;
    const int ecol = (lane & 3) * 2;
#pragma unroll
    for (int mf = 0; mf < 4; ++mf) {
#pragma unroll
        for (int half = 0; half < 2; ++half) {
            int m = row0 + wm0 + mf * 16 + erow + half * 8;
            int b_ = m >> 11, t = m & (TT - 1);
#pragma unroll
            for (int nf = 0; nf < 4; ++nf) {
                int n = col0 + wn0 + nf * 8 + ecol;
                float vx = acc[mf][nf][half * 2 + 0] + bias[n + 0];
                float vy = acc[mf][nf][half * 2 + 1] + bias[n + 1];
                if (MODE == 0) {
                    float2 v = {vx, vy};
                    *(float2*)(Cout + (size_t)m * DIMC + n) = v;
                } else {
                    int sec = n >> 10;
                    int cc = n & (DIMC - 1);
                    int h = cc >> 6, d = cc & 63;
                    size_t idx = (((size_t)(b_ * NH + h)) * TT + t) * HD + d;
                    uint32_t hi, lo;
                    if (sec == 0) {
                        float qx = (vx + pos[cc + 0]) * QSCALE;
                        float qy = (vy + pos[cc + 1]) * QSCALE;
                        split2h(qx, qy, hi, lo);
                        *(uint32_t*)(g_qh + idx) = hi;
                        *(uint32_t*)(g_ql + idx) = lo;
                    } else if (sec == 1) {
                        split2h(vx, vy, hi, lo);
                        *(uint32_t*)(g_kh + idx) = hi;
                        *(uint32_t*)(g_kl + idx) = lo;
                    } else {
                        split2h(vx, vy, hi, lo);
                        *(uint32_t*)(g_vh + idx) = hi;
                        *(uint32_t*)(g_vl + idx) = lo;
                    }
                }
            }
        }
    }
}

// ============================================================================
// HMMA flash attention. CTA: 128 q-rows, 8 warps x 16 rows, Bc=64 keys.
// fp16 split QK^T (3 products) + exp2 poly softmax + fp16 split PV (3 products).
// Writes bf16 hi/lo attention output for the out-projection GEMM.
// ============================================================================
#define AT_PADH 72                      // fp16 elems per smem row (144 B)
#define Q_BYTES (128 * AT_PADH * 2)     // 18432
#define KV_MAT  (64 * AT_PADH * 2)      // 9216
#define KV_STAGE (4 * KV_MAT)           // 36864
#define ATT_SMEM (2 * Q_BYTES + 2 * KV_STAGE)   // 110592

__global__ __launch_bounds__(256) void attn2()
{
    extern __shared__ char smraw[];
    const uint32_t sb = smem_u32(smraw);
    const uint32_t sQh = sb, sQl = sb + Q_BYTES;
    const uint32_t sKV = sb + 2 * Q_BYTES;

    const int tid = threadIdx.x;
    const int lane = tid & 31;
    const int qi = gridDim.x - 1 - blockIdx.x;   // heavy tiles first
    const int bh = blockIdx.y;
    const int q0 = qi * 128;
    const int qr0 = (tid >> 5) * 16;             // warp's q-row base within tile

    const __half* qhp = g_qh + (size_t)bh * TT * HD;
    const __half* qlp = g_ql + (size_t)bh * TT * HD;
    const __half* kvsrc[4] = {
        g_kh + (size_t)bh * TT * HD, g_kl + (size_t)bh * TT * HD,
        g_vh + (size_t)bh * TT * HD, g_vl + (size_t)bh * TT * HD };

    auto prefetchKV = [&](int j, uint32_t dst) {
        int kb = j * 64;
#pragma unroll
        for (int i = 0; i < 8; ++i) {
            int c = tid + i * 256;
            int mat = c >> 9, rem = c & 511;
            int r = rem >> 3, ch = rem & 7;
            cp16(dst + (uint32_t)mat * KV_MAT + (uint32_t)(r * 144 + ch * 16),
                 kvsrc[mat] + (size_t)(kb + r) * HD + ch * 8);
        }
    };

    // Q tile + first K/V tile
#pragma unroll
    for (int i = 0; i < 4; ++i) {
        int c = tid + i * 256;
        int r = c >> 3, ch = c & 7;
        cp16(sQh + (uint32_t)(r * 144 + ch * 16), qhp + (size_t)(q0 + r) * HD + ch * 8);
        cp16(sQl + (uint32_t)(r * 144 + ch * 16), qlp + (size_t)(q0 + r) * HD + ch * 8);
    }
    prefetchKV(0, sKV);
    cp_commit();
    cp_wait0();
    __syncthreads();

    // persistent Q fragments
    uint32_t fqh[4][4], fql[4][4];
    {
        int rr = qr0 + (lane & 15);
#pragma unroll
        for (int kf = 0; kf < 4; ++kf) {
            int cc = kf * 16 + ((lane & 16) ? 8 : 0);
            uint32_t off = (uint32_t)(rr * 144 + cc * 2);
            ldsm4(fqh[kf][0], fqh[kf][1], fqh[kf][2], fqh[kf][3], sQh + off);
            ldsm4(fql[kf][0], fql[kf][1], fql[kf][2], fql[kf][3], sQl + off);
        }
    }

    float o[8][4];
#pragma unroll
    for (int i = 0; i < 8; ++i)
#pragma unroll
        for (int k = 0; k < 4; ++k) o[i][k] = 0.0f;
    float m0 = -1e30f, m1 = -1e30f, l0 = 0.0f, l1 = 0.0f;

    const int ntiles = 2 * qi + 2;
    for (int j = 0; j < ntiles; ++j) {
        uint32_t stage = sKV + (uint32_t)(j & 1) * KV_STAGE;
        if (j + 1 < ntiles) {
            prefetchKV(j + 1, sKV + (uint32_t)((j + 1) & 1) * KV_STAGE);
            cp_commit();
        }

        // ---- S = Qh Kh^T + Ql Kh^T + Qh Kl^T ----
        float c[8][4];
#pragma unroll
        for (int i = 0; i < 8; ++i)
#pragma unroll
            for (int k = 0; k < 4; ++k) c[i][k] = 0.0f;

        uint32_t Kh = stage, Kl = stage + KV_MAT;
        {
            int rb = ((lane & 16) ? 8 : 0) + (lane & 7);
            int cb = ((lane & 8) ? 8 : 0);
#pragma unroll
            for (int kf = 0; kf < 4; ++kf) {
#pragma unroll
                for (int jp = 0; jp < 4; ++jp) {
                    uint32_t off = (uint32_t)((jp * 16 + rb) * 144 + (kf * 16 + cb) * 2);
                    uint32_t h0, h1, h2, h3, l0r, l1r, l2r, l3r;
                    ldsm4(h0, h1, h2, h3, Kh + off);
                    ldsm4(l0r, l1r, l2r, l3r, Kl + off);
                    mma_fp(c[2 * jp],     fqh[kf], h0, h1);
                    mma_fp(c[2 * jp],     fql[kf], h0, h1);
                    mma_fp(c[2 * jp],     fqh[kf], l0r, l1r);
                    mma_fp(c[2 * jp + 1], fqh[kf], h2, h3);
                    mma_fp(c[2 * jp + 1], fql[kf], h2, h3);
                    mma_fp(c[2 * jp + 1], fqh[kf], l2r, l3r);
                }
            }
        }

        // ---- causal mask (only last two tiles) ----
        if (j >= 2 * qi) {
            int row0 = q0 + qr0 + (lane >> 2);
            int kb = j * 64 + (lane & 3) * 2;
#pragma unroll
            for (int nf = 0; nf < 8; ++nf) {
                int key = kb + nf * 8;
                if (key     > row0)     c[nf][0] = -1e30f;
                if (key + 1 > row0)     c[nf][1] = -1e30f;
                if (key     > row0 + 8) c[nf][2] = -1e30f;
                if (key + 1 > row0 + 8) c[nf][3] = -1e30f;
            }
        }

        // ---- online softmax ----
        float v0 = -1e30f, v1 = -1e30f;
#pragma unroll
        for (int nf = 0; nf < 8; ++nf) {
            v0 = fmaxf(v0, fmaxf(c[nf][0], c[nf][1]));
            v1 = fmaxf(v1, fmaxf(c[nf][2], c[nf][3]));
        }
        v0 = fmaxf(v0, __shfl_xor_sync(0xFFFFFFFFu, v0, 1));
        v0 = fmaxf(v0, __shfl_xor_sync(0xFFFFFFFFu, v0, 2));
        v1 = fmaxf(v1, __shfl_xor_sync(0xFFFFFFFFu, v1, 1));
        v1 = fmaxf(v1, __shfl_xor_sync(0xFFFFFFFFu, v1, 2));
        float mn0 = fmaxf(m0, v0), mn1 = fmaxf(m1, v1);
        float a0 = exp2p(m0 - mn0), a1 = exp2p(m1 - mn1);
        m0 = mn0; m1 = mn1;
        l0 *= a0; l1 *= a1;
#pragma unroll
        for (int nf = 0; nf < 8; ++nf) {
            o[nf][0] *= a0; o[nf][1] *= a0;
            o[nf][2] *= a1; o[nf][3] *= a1;
        }

        // ---- P (exp2 poly) + PV per 16-key fragment ----
        uint32_t Vh = stage + 2 * KV_MAT, Vl = stage + 3 * KV_MAT;
        int vrb = ((lane & 8) ? 8 : 0) + (lane & 7);
        int vcb = ((lane & 16) ? 8 : 0);
#pragma unroll
        for (int t = 0; t < 4; ++t) {
            float p00 = exp2p(c[2 * t][0] - m0), p01 = exp2p(c[2 * t][1] - m0);
            float p02 = exp2p(c[2 * t][2] - m1), p03 = exp2p(c[2 * t][3] - m1);
            float p10 = exp2p(c[2 * t + 1][0] - m0), p11 = exp2p(c[2 * t + 1][1] - m0);
            float p12 = exp2p(c[2 * t + 1][2] - m1), p13 = exp2p(c[2 * t + 1][3] - m1);
            l0 += p00 + p01 + p10 + p11;
            l1 += p02 + p03 + p12 + p13;

            uint32_t ph[4], pl[4];
            split2h(p00, p01, ph[0], pl[0]);
            split2h(p02, p03, ph[1], pl[1]);
            split2h(p10, p11, ph[2], pl[2]);
            split2h(p12, p13, ph[3], pl[3]);

#pragma unroll
            for (int dp = 0; dp < 4; ++dp) {
                uint32_t off = (uint32_t)((t * 16 + vrb) * 144 + (dp * 16 + vcb) * 2);
                uint32_t h0, h1, h2, h3, w0, w1, w2, w3;
                ldsm4t(h0, h1, h2, h3, Vh + off);
                ldsm4t(w0, w1, w2, w3, Vl + off);
                mma_fp(o[2 * dp],     ph, h0, h1);
                mma_fp(o[2 * dp],     pl, h0, h1);
                mma_fp(o[2 * dp],     ph, w0, w1);
                mma_fp(o[2 * dp + 1], ph, h2, h3);
                mma_fp(o[2 * dp + 1], pl, h2, h3);
                mma_fp(o[2 * dp + 1], ph, w2, w3);
            }
        }

        if (j + 1 < ntiles) cp_wait0();
        __syncthreads();
    }

    // ---- epilogue: normalize, write bf16 hi/lo [B,T,C] ----
    l0 += __shfl_xor_sync(0xFFFFFFFFu, l0, 1);
    l0 += __shfl_xor_sync(0xFFFFFFFFu, l0, 2);
    l1 += __shfl_xor_sync(0xFFFFFFFFu, l1, 1);
    l1 += __shfl_xor_sync(0xFFFFFFFFu, l1, 2);
    float inv0 = 1.0f / l0, inv1 = 1.0f / l1;

    int b_ = bh >> 4, h = bh & 15;
    int t0 = q0 + qr0 + (lane >> 2);
    size_t r0 = ((size_t)b_ * TT + t0) * DIMC;
    size_t r1 = r0 + (size_t)8 * DIMC;
    int coff = h * 64 + (lane & 3) * 2;
#pragma unroll
    for (int nf = 0; nf < 8; ++nf) {
        int col = coff + nf * 8;
        float x0 = o[nf][0] * inv0, y0 = o[nf][1] * inv0;
        float x1 = o[nf][2] * inv1, y1 = o[nf][3] * inv1;
        __nv_bfloat16 hx0 = __float2bfloat16(x0), hy0 = __float2bfloat16(y0);
        __nv_bfloat16 hx1 = __float2bfloat16(x1), hy1 = __float2bfloat16(y1);
        __nv_bfloat162 hi0 = {hx0, hy0}, hi1 = {hx1, hy1};
        __nv_bfloat162 lo0 = {__float2bfloat16(x0 - __bfloat162float(hx0)),
                              __float2bfloat16(y0 - __bfloat162float(hy0))};
        __nv_bfloat162 lo1 = {__float2bfloat16(x1 - __bfloat162float(hx1)),
                              __float2bfloat16(y1 - __bfloat162float(hy1))};
        *(__nv_bfloat162*)(g_ah + r0 + col) = hi0;
        *(__nv_bfloat162*)(g_al + r0 + col) = lo0;
        *(__nv_bfloat162*)(g_ah + r1 + col) = hi1;
        *(__nv_bfloat162*)(g_al + r1 + col) = lo1;
    }
}

// ============================================================================
// Launch
// ============================================================================
extern "C" void kernel_launch(void* const* d_in, const int* in_sizes, int n_in,
                              void* d_out, int out_size)
{
    (void)in_sizes; (void)n_in; (void)out_size;
    const float* x     = (const float*)d_in[0];
    const float* w_qkv = (const float*)d_in[1];
    const float* b_qkv = (const float*)d_in[2];
    const float* w_out = (const float*)d_in[3];
    const float* b_out = (const float*)d_in[4];
    const float* pos   = (const float*)d_in[5];
    float* out = (float*)d_out;

    cudaFuncSetAttribute(hmma_gemm<1>, cudaFuncAttributeMaxDynamicSharedMemorySize, GEMM_SMEM);
    cudaFuncSetAttribute(hmma_gemm<0>, cudaFuncAttributeMaxDynamicSharedMemorySize, GEMM_SMEM);
    cudaFuncSetAttribute(attn2, cudaFuncAttributeMaxDynamicSharedMemorySize, ATT_SMEM);

    // 0) split input + transpose/split weights
    split_kernel<<<MTOT * DIMC / 256, 256>>>(x);
    transpose_split<0><<<dim3(N_QKV / 32, DIMC / 32), dim3(32, 8)>>>(w_qkv);
    transpose_split<1><<<dim3(DIMC / 32, DIMC / 32), dim3(32, 8)>>>(w_out);

    // 1) QKV projection + bias (+pos, q-scale) -> fp16 split Q/K/V
    hmma_gemm<1><<<dim3(N_QKV / 128, MTOT / 128), 256, GEMM_SMEM>>>(b_qkv, pos, nullptr);

    // 2) HMMA flash attention -> bf16 split attn out
    attn2<<<dim3(TT / 128, BB * NH), 256, ATT_SMEM>>>();

    // 3) output projection + bias
    hmma_gemm<0><<<dim3(DIMC / 128, MTOT / 128), 256, GEMM_SMEM>>>(b_out, nullptr, out);
}